// round 1
// baseline (speedup 1.0000x reference)
#include <cuda_runtime.h>
#include <math.h>

#define BB 2
#define SS 1024
#define HID 4096
#define NH 32
#define NKV 8
#define HD 128
#define LCK 3
#define MROWS (BB*SS)   // 2048
#define QDIM (NH*HD)    // 4096
#define KVDIM (NKV*HD)  // 1024

// ---------------- scratch (static device globals; no allocations) ----------
__device__ float g_q[(size_t)MROWS * QDIM];     // 32 MB
__device__ float g_k[(size_t)MROWS * KVDIM];    // 8 MB
__device__ float g_v[(size_t)MROWS * KVDIM];    // 8 MB
__device__ float g_attn[(size_t)MROWS * QDIM];  // 32 MB

// ---------------- classic fp32 SGEMM: 128x128 tile, BK=8, 256 thr ----------
// A: [M,K] row-major, B: [K,N] row-major, C: [M,N] row-major.
// All of M,N,K are multiples of 128/8 here, so no bounds checks.
__global__ void sgemm128(const float* __restrict__ A,
                         const float* __restrict__ B,
                         float* __restrict__ C,
                         int M, int N, int K) {
    __shared__ float As[8][128];
    __shared__ float Bs[8][128];

    const int tid = threadIdx.x;          // 0..255
    const int tx = tid & 15;              // 16 cols of threads
    const int ty = tid >> 4;              // 16 rows of threads

    // A tile loader: 128 rows x 8 k; one float4 per thread
    const int arow = tid >> 1;            // 0..127
    const int acol = (tid & 1) * 4;       // 0 or 4
    // B tile loader: 8 k x 128 cols; one float4 per thread
    const int brow = tid >> 6;            // 0..3  (4 rows of float4 per pass? no:)
    // 8 rows * 32 float4 = 256 float4 -> brow = tid>>5 (0..7), bcol = (tid&31)*4
    const int brow8 = tid >> 5;           // 0..7
    const int bcol  = (tid & 31) * 4;

    (void)brow;

    const float* Aptr = A + (size_t)(blockIdx.y * 128 + arow) * K;
    const float* Bptr = B + (size_t)blockIdx.x * 128;

    float acc[8][8];
#pragma unroll
    for (int i = 0; i < 8; i++)
#pragma unroll
        for (int j = 0; j < 8; j++) acc[i][j] = 0.f;

    for (int k0 = 0; k0 < K; k0 += 8) {
        float4 a4 = *(const float4*)(Aptr + k0 + acol);
        As[acol + 0][arow] = a4.x;
        As[acol + 1][arow] = a4.y;
        As[acol + 2][arow] = a4.z;
        As[acol + 3][arow] = a4.w;
        float4 b4 = *(const float4*)(Bptr + (size_t)(k0 + brow8) * N + bcol);
        *(float4*)&Bs[brow8][bcol] = b4;
        __syncthreads();

#pragma unroll
        for (int kk = 0; kk < 8; kk++) {
            float ar[8], br[8];
#pragma unroll
            for (int i = 0; i < 8; i++) ar[i] = As[kk][ty * 8 + i];
#pragma unroll
            for (int j = 0; j < 8; j++) br[j] = Bs[kk][tx * 8 + j];
#pragma unroll
            for (int i = 0; i < 8; i++)
#pragma unroll
                for (int j = 0; j < 8; j++) acc[i][j] = fmaf(ar[i], br[j], acc[i][j]);
        }
        __syncthreads();
    }

    float* Cptr = C + (size_t)(blockIdx.y * 128 + ty * 8) * N + blockIdx.x * 128 + tx * 8;
#pragma unroll
    for (int i = 0; i < 8; i++) {
        *(float4*)(Cptr + (size_t)i * N + 0) =
            make_float4(acc[i][0], acc[i][1], acc[i][2], acc[i][3]);
        *(float4*)(Cptr + (size_t)i * N + 4) =
            make_float4(acc[i][4], acc[i][5], acc[i][6], acc[i][7]);
    }
}

// ---------------- RoPE (in-place, layout [MROWS, heads*128]) ---------------
__global__ void rope_kernel(float* __restrict__ buf, int heads) {
    const int row = blockIdx.x;            // 0..2047
    const int s = row & (SS - 1);          // position
    const float log2theta = 13.287712379549449f;  // log2(10000)
    for (int idx = threadIdx.x; idx < heads * 64; idx += blockDim.x) {
        const int h = idx >> 6;
        const int i = idx & 63;
        // inv_freq = 10000^(-2i/128)
        const float inv = exp2f(-(float)(2 * i) * (1.0f / 128.0f) * log2theta);
        const float ang = (float)s * inv;
        const float c = cosf(ang);
        const float sn = sinf(ang);
        float* p = buf + (size_t)row * heads * HD + h * HD;
        const float x1 = p[i];
        const float x2 = p[i + 64];
        p[i]      = x1 * c - x2 * sn;
        p[i + 64] = x2 * c + x1 * sn;
    }
}

// ---------------- flash attention ------------------------------------------
// grid: (S/32, NH, B), block: 256 = 32 queries x 8 dim-lanes.
// Thread (ql, sub) owns dims d = t*32 + sub*4 + i  (t=0..3, i=0..3)
// -> conflict-free smem reads (all 32 banks per LDS.128 phase), coalesced GMEM.
__global__ void attn_kernel(const float* __restrict__ q,
                            const float* __restrict__ k,
                            const float* __restrict__ v,
                            const float* __restrict__ ksuf,
                            const float* __restrict__ vsuf,
                            const int* __restrict__ validp,
                            float* __restrict__ outbuf) {
    __shared__ float Ks[32][128];
    __shared__ float Vs[32][128];

    const int valid = *validp;
    const int qt = blockIdx.x;
    const int h  = blockIdx.y;
    const int b  = blockIdx.z;
    const int kvh = h >> 2;

    const int tid = threadIdx.x;
    const int ql  = tid >> 3;      // 0..31
    const int sub = tid & 7;       // 0..7
    const int q_global = qt * 32 + ql;
    const bool qvalid = q_global < valid;

    const float scale = 0.08838834764831845f;  // 1/sqrt(128)

    // load q fragment (pre-scaled)
    float qr[4][4];
    {
        const float* qp = q + (size_t)(b * SS + q_global) * QDIM + h * HD;
#pragma unroll
        for (int t = 0; t < 4; t++) {
            float4 f = *(const float4*)(qp + t * 32 + sub * 4);
            qr[t][0] = f.x * scale; qr[t][1] = f.y * scale;
            qr[t][2] = f.z * scale; qr[t][3] = f.w * scale;
        }
    }

    float o[4][4];
#pragma unroll
    for (int t = 0; t < 4; t++)
#pragma unroll
        for (int i = 0; i < 4; i++) o[t][i] = 0.f;
    float m = -1e30f, l = 0.f;

    const int kend = qt * 32 + 32;  // keys needed by this q tile (causal)
    const float* kb_base = k + (size_t)(b * SS) * KVDIM + kvh * HD;
    const float* vb_base = v + (size_t)(b * SS) * KVDIM + kvh * HD;

    for (int k0 = 0; k0 < kend; k0 += 32) {
        // cooperative tile load: 1024 float4s, 4 per thread, coalesced
#pragma unroll
        for (int t = 0; t < 4; t++) {
            const int f  = tid + t * 256;
            const int kk = f >> 5;
            const int d4 = (f & 31) * 4;
            *(float4*)&Ks[kk][d4] =
                *(const float4*)(kb_base + (size_t)(k0 + kk) * KVDIM + d4);
            *(float4*)&Vs[kk][d4] =
                *(const float4*)(vb_base + (size_t)(k0 + kk) * KVDIM + d4);
        }
        __syncthreads();

        float sc[32];
#pragma unroll 8
        for (int kk = 0; kk < 32; kk++) {
            float p = 0.f;
#pragma unroll
            for (int t = 0; t < 4; t++) {
                float4 kv4 = *(const float4*)&Ks[kk][t * 32 + sub * 4];
                p = fmaf(qr[t][0], kv4.x, p);
                p = fmaf(qr[t][1], kv4.y, p);
                p = fmaf(qr[t][2], kv4.z, p);
                p = fmaf(qr[t][3], kv4.w, p);
            }
            p += __shfl_xor_sync(0xffffffffu, p, 1);
            p += __shfl_xor_sync(0xffffffffu, p, 2);
            p += __shfl_xor_sync(0xffffffffu, p, 4);
            sc[kk] = (k0 + kk <= q_global) ? p : -1e30f;
        }

        float tmax = sc[0];
#pragma unroll
        for (int kk = 1; kk < 32; kk++) tmax = fmaxf(tmax, sc[kk]);
        const float mnew = fmaxf(m, tmax);
        const float corr = __expf(m - mnew);
        l *= corr;
#pragma unroll
        for (int t = 0; t < 4; t++)
#pragma unroll
            for (int i = 0; i < 4; i++) o[t][i] *= corr;

#pragma unroll 8
        for (int kk = 0; kk < 32; kk++) {
            const float p = __expf(sc[kk] - mnew);
            l += p;
#pragma unroll
            for (int t = 0; t < 4; t++) {
                float4 vv = *(const float4*)&Vs[kk][t * 32 + sub * 4];
                o[t][0] = fmaf(p, vv.x, o[t][0]);
                o[t][1] = fmaf(p, vv.y, o[t][1]);
                o[t][2] = fmaf(p, vv.z, o[t][2]);
                o[t][3] = fmaf(p, vv.w, o[t][3]);
            }
        }
        m = mnew;
        __syncthreads();
    }

    // ---- 3 suffix keys on the diagonal: k_suffix[b, kvh, j, q_global, :] ----
#pragma unroll
    for (int j = 0; j < LCK; j++) {
        const size_t off =
            (((size_t)(b * NKV + kvh) * LCK + j) * SS + q_global) * HD;
        const float* kp = ksuf + off;
        float p = 0.f;
#pragma unroll
        for (int t = 0; t < 4; t++) {
            float4 kv4 = *(const float4*)(kp + t * 32 + sub * 4);
            p = fmaf(qr[t][0], kv4.x, p);
            p = fmaf(qr[t][1], kv4.y, p);
            p = fmaf(qr[t][2], kv4.z, p);
            p = fmaf(qr[t][3], kv4.w, p);
        }
        p += __shfl_xor_sync(0xffffffffu, p, 1);
        p += __shfl_xor_sync(0xffffffffu, p, 2);
        p += __shfl_xor_sync(0xffffffffu, p, 4);

        const float mnew = fmaxf(m, p);
        const float corr = __expf(m - mnew);
        const float e = __expf(p - mnew);
        l = l * corr + e;
        const float* vp = vsuf + off;
#pragma unroll
        for (int t = 0; t < 4; t++) {
            float4 vv = *(const float4*)(vp + t * 32 + sub * 4);
            o[t][0] = o[t][0] * corr + e * vv.x;
            o[t][1] = o[t][1] * corr + e * vv.y;
            o[t][2] = o[t][2] * corr + e * vv.z;
            o[t][3] = o[t][3] * corr + e * vv.w;
        }
        m = mnew;
    }

    // epilogue: normalize; masked (invalid) queries output zeros
    const float invl = qvalid ? (1.0f / l) : 0.0f;
    float* op = outbuf + (size_t)(b * SS + q_global) * QDIM + h * HD;
#pragma unroll
    for (int t = 0; t < 4; t++) {
        float4 w;
        w.x = o[t][0] * invl; w.y = o[t][1] * invl;
        w.z = o[t][2] * invl; w.w = o[t][3] * invl;
        *(float4*)(op + t * 32 + sub * 4) = w;
    }
}

// ---------------- launch ----------------------------------------------------
extern "C" void kernel_launch(void* const* d_in, const int* in_sizes, int n_in,
                              void* d_out, int out_size) {
    const float* x    = (const float*)d_in[0];  // [2,1024,4096]
    const float* ksuf = (const float*)d_in[1];  // [2,8,3,1024,128]
    const float* vsuf = (const float*)d_in[2];
    const float* Wq   = (const float*)d_in[3];  // [4096,4096]
    const float* Wk   = (const float*)d_in[4];  // [4096,1024]
    const float* Wv   = (const float*)d_in[5];
    const float* Wo   = (const float*)d_in[6];  // [4096,4096]
    const int* valid  = (const int*)d_in[7];    // scalar
    float* out = (float*)d_out;                 // [2,1024,4096]

    float *gq, *gk, *gv, *ga;
    cudaGetSymbolAddress((void**)&gq, g_q);
    cudaGetSymbolAddress((void**)&gk, g_k);
    cudaGetSymbolAddress((void**)&gv, g_v);
    cudaGetSymbolAddress((void**)&ga, g_attn);

    dim3 blk(256);

    // projections
    sgemm128<<<dim3(QDIM / 128, MROWS / 128), blk>>>(x, Wq, gq, MROWS, QDIM, HID);
    sgemm128<<<dim3(KVDIM / 128, MROWS / 128), blk>>>(x, Wk, gk, MROWS, KVDIM, HID);
    sgemm128<<<dim3(KVDIM / 128, MROWS / 128), blk>>>(x, Wv, gv, MROWS, KVDIM, HID);

    // RoPE on q and k
    rope_kernel<<<MROWS, 256>>>(gq, NH);
    rope_kernel<<<MROWS, 256>>>(gk, NKV);

    // attention
    attn_kernel<<<dim3(SS / 32, NH, BB), 256>>>(gq, gk, gv, ksuf, vsuf, valid, ga);

    // output projection
    sgemm128<<<dim3(QDIM / 128, MROWS / 128), blk>>>(ga, Wo, out, MROWS, QDIM, HID);
}

// round 2
// speedup vs baseline: 2.4251x; 2.4251x over previous
#include <cuda_runtime.h>
#include <math.h>
#include <stdint.h>

#define BB 2
#define SS 1024
#define HID 4096
#define NH 32
#define NKV 8
#define HD 128
#define LCK 3
#define MROWS (BB*SS)   // 2048
#define QDIM (NH*HD)    // 4096
#define KVDIM (NKV*HD)  // 1024

// GEMM tiling
#define BM 128
#define BN 128
#define BK 32
#define APAD 36   // 32 + 4
#define BPAD 132  // 128 + 4
#define GEMM_SMEM ((2*BM*APAD + 2*BK*BPAD) * 4)  // 70656 bytes

// ---------------- scratch (static device globals; no allocations) ----------
__device__ float g_q[(size_t)MROWS * QDIM];     // 32 MB
__device__ float g_k[(size_t)MROWS * KVDIM];    // 8 MB
__device__ float g_v[(size_t)MROWS * KVDIM];    // 8 MB
__device__ float g_attn[(size_t)MROWS * QDIM];  // 32 MB

// ---------------- helpers ----------------------------------------------------
__device__ __forceinline__ void cp16(uint32_t dst, const void* src) {
    asm volatile("cp.async.cg.shared.global [%0], [%1], 16;" :: "r"(dst), "l"(src));
}
__device__ __forceinline__ uint32_t f2tf32(float x) {
    uint32_t u;
    asm("cvt.rna.tf32.f32 %0, %1;" : "=r"(u) : "f"(x));
    return u;
}
__device__ __forceinline__ void mma_tf32(float* c, const uint32_t* a, const uint32_t* b) {
    asm volatile(
        "mma.sync.aligned.m16n8k8.row.col.f32.tf32.tf32.f32 "
        "{%0,%1,%2,%3},{%4,%5,%6,%7},{%8,%9},{%0,%1,%2,%3};"
        : "+f"(c[0]), "+f"(c[1]), "+f"(c[2]), "+f"(c[3])
        : "r"(a[0]), "r"(a[1]), "r"(a[2]), "r"(a[3]), "r"(b[0]), "r"(b[1]));
}

// ---------------- TF32 tensor-core GEMM: 128x128x32, 256 thr ----------------
// A: [M,K] row-major, B: [K,N] row-major, C: [M,N] row-major.
// M,N multiples of 128; K multiple of 32.
__global__ __launch_bounds__(256) void gemm_tf32(const float* __restrict__ A,
                                                 const float* __restrict__ B,
                                                 float* __restrict__ C,
                                                 int M, int N, int K) {
    extern __shared__ float sm[];
    float (*As)[BM][APAD]  = (float (*)[BM][APAD])sm;               // [2][128][36]
    float (*Bs)[BK][BPAD]  = (float (*)[BK][BPAD])(sm + 2*BM*APAD); // [2][32][132]

    const int tid  = threadIdx.x;
    const int lane = tid & 31;
    const int wid  = tid >> 5;
    const int wm   = (wid & 3) * 32;   // warp row offset (4 warps along M)
    const int wn   = (wid >> 2) * 64;  // warp col offset (2 warps along N)
    const int gid  = lane >> 2;        // 0..7
    const int tig  = lane & 3;         // 0..3

    const int bm0 = blockIdx.y * BM;
    const int bn0 = blockIdx.x * BN;

    const uint32_t sA = (uint32_t)__cvta_generic_to_shared(&As[0][0][0]);
    const uint32_t sB = (uint32_t)__cvta_generic_to_shared(&Bs[0][0][0]);

    // per-thread loader coords
    const int am  = tid >> 1;              // A: handled below via idx scheme
    (void)am;

    float acc[2][8][4];
#pragma unroll
    for (int mt = 0; mt < 2; mt++)
#pragma unroll
        for (int nt = 0; nt < 8; nt++)
#pragma unroll
            for (int i = 0; i < 4; i++) acc[mt][nt][i] = 0.f;

    const int T = K / BK;

    // ---- tile issue (cp.async) ----
    auto issue = [&](int t, int buf) {
#pragma unroll
        for (int i = 0; i < 4; i++) {
            const int idx = tid + i * 256;         // 0..1023
            const int m  = idx >> 3;               // 0..127
            const int kq = (idx & 7) * 4;          // 0,4,..28
            cp16(sA + (uint32_t)(((buf * BM + m) * APAD + kq) * 4),
                 A + (size_t)(bm0 + m) * K + t * BK + kq);
        }
#pragma unroll
        for (int i = 0; i < 4; i++) {
            const int idx = tid + i * 256;
            const int kk = idx >> 5;               // 0..31
            const int nq = (idx & 31) * 4;         // 0..124
            cp16(sB + (uint32_t)(((buf * BK + kk) * BPAD + nq) * 4),
                 B + (size_t)(t * BK + kk) * N + bn0 + nq);
        }
    };

    issue(0, 0);
    asm volatile("cp.async.commit_group;");

    for (int t = 0; t < T; t++) {
        const int buf = t & 1;
        if (t + 1 < T) {
            issue(t + 1, (t + 1) & 1);
            asm volatile("cp.async.commit_group;");
            asm volatile("cp.async.wait_group 1;");
        } else {
            asm volatile("cp.async.wait_group 0;");
        }
        __syncthreads();

#pragma unroll
        for (int ks = 0; ks < BK; ks += 8) {
            uint32_t af[2][4];
#pragma unroll
            for (int mt = 0; mt < 2; mt++) {
                const int r = wm + mt * 16 + gid;
                af[mt][0] = f2tf32(As[buf][r][ks + tig]);
                af[mt][1] = f2tf32(As[buf][r + 8][ks + tig]);
                af[mt][2] = f2tf32(As[buf][r][ks + tig + 4]);
                af[mt][3] = f2tf32(As[buf][r + 8][ks + tig + 4]);
            }
            uint32_t bf[8][2];
#pragma unroll
            for (int nt = 0; nt < 8; nt++) {
                const int c = wn + nt * 8 + gid;
                bf[nt][0] = f2tf32(Bs[buf][ks + tig][c]);
                bf[nt][1] = f2tf32(Bs[buf][ks + tig + 4][c]);
            }
#pragma unroll
            for (int mt = 0; mt < 2; mt++)
#pragma unroll
                for (int nt = 0; nt < 8; nt++)
                    mma_tf32(acc[mt][nt], af[mt], bf[nt]);
        }
        __syncthreads();
    }

    // ---- epilogue ----
    float* Cp = C + (size_t)(bm0 + wm) * N + bn0 + wn;
#pragma unroll
    for (int mt = 0; mt < 2; mt++) {
#pragma unroll
        for (int nt = 0; nt < 8; nt++) {
            const int r = mt * 16 + gid;
            const int c = nt * 8 + tig * 2;
            *(float2*)&Cp[(size_t)r * N + c] =
                make_float2(acc[mt][nt][0], acc[mt][nt][1]);
            *(float2*)&Cp[(size_t)(r + 8) * N + c] =
                make_float2(acc[mt][nt][2], acc[mt][nt][3]);
        }
    }
}

// ---------------- RoPE (in-place, layout [MROWS, heads*128]) ---------------
__global__ void rope_kernel(float* __restrict__ buf, int heads) {
    const int row = blockIdx.x;
    const int s = row & (SS - 1);
    const float log2theta = 13.287712379549449f;  // log2(10000)
    for (int idx = threadIdx.x; idx < heads * 64; idx += blockDim.x) {
        const int h = idx >> 6;
        const int i = idx & 63;
        const float inv = exp2f(-(float)(2 * i) * (1.0f / 128.0f) * log2theta);
        const float ang = (float)s * inv;
        const float c = cosf(ang);
        const float sn = sinf(ang);
        float* p = buf + (size_t)row * heads * HD + h * HD;
        const float x1 = p[i];
        const float x2 = p[i + 64];
        p[i]      = x1 * c - x2 * sn;
        p[i + 64] = x2 * c + x1 * sn;
    }
}

// ---------------- flash attention (fp32, unchanged from R1) ----------------
__global__ void attn_kernel(const float* __restrict__ q,
                            const float* __restrict__ k,
                            const float* __restrict__ v,
                            const float* __restrict__ ksuf,
                            const float* __restrict__ vsuf,
                            const int* __restrict__ validp,
                            float* __restrict__ outbuf) {
    __shared__ float Ks[32][128];
    __shared__ float Vs[32][128];

    const int valid = *validp;
    const int qt = blockIdx.x;
    const int h  = blockIdx.y;
    const int b  = blockIdx.z;
    const int kvh = h >> 2;

    const int tid = threadIdx.x;
    const int ql  = tid >> 3;
    const int sub = tid & 7;
    const int q_global = qt * 32 + ql;
    const bool qvalid = q_global < valid;

    const float scale = 0.08838834764831845f;

    float qr[4][4];
    {
        const float* qp = q + (size_t)(b * SS + q_global) * QDIM + h * HD;
#pragma unroll
        for (int t = 0; t < 4; t++) {
            float4 f = *(const float4*)(qp + t * 32 + sub * 4);
            qr[t][0] = f.x * scale; qr[t][1] = f.y * scale;
            qr[t][2] = f.z * scale; qr[t][3] = f.w * scale;
        }
    }

    float o[4][4];
#pragma unroll
    for (int t = 0; t < 4; t++)
#pragma unroll
        for (int i = 0; i < 4; i++) o[t][i] = 0.f;
    float m = -1e30f, l = 0.f;

    const int kend = qt * 32 + 32;
    const float* kb_base = k + (size_t)(b * SS) * KVDIM + kvh * HD;
    const float* vb_base = v + (size_t)(b * SS) * KVDIM + kvh * HD;

    for (int k0 = 0; k0 < kend; k0 += 32) {
#pragma unroll
        for (int t = 0; t < 4; t++) {
            const int f  = tid + t * 256;
            const int kk = f >> 5;
            const int d4 = (f & 31) * 4;
            *(float4*)&Ks[kk][d4] =
                *(const float4*)(kb_base + (size_t)(k0 + kk) * KVDIM + d4);
            *(float4*)&Vs[kk][d4] =
                *(const float4*)(vb_base + (size_t)(k0 + kk) * KVDIM + d4);
        }
        __syncthreads();

        float sc[32];
#pragma unroll 8
        for (int kk = 0; kk < 32; kk++) {
            float p = 0.f;
#pragma unroll
            for (int t = 0; t < 4; t++) {
                float4 kv4 = *(const float4*)&Ks[kk][t * 32 + sub * 4];
                p = fmaf(qr[t][0], kv4.x, p);
                p = fmaf(qr[t][1], kv4.y, p);
                p = fmaf(qr[t][2], kv4.z, p);
                p = fmaf(qr[t][3], kv4.w, p);
            }
            p += __shfl_xor_sync(0xffffffffu, p, 1);
            p += __shfl_xor_sync(0xffffffffu, p, 2);
            p += __shfl_xor_sync(0xffffffffu, p, 4);
            sc[kk] = (k0 + kk <= q_global) ? p : -1e30f;
        }

        float tmax = sc[0];
#pragma unroll
        for (int kk = 1; kk < 32; kk++) tmax = fmaxf(tmax, sc[kk]);
        const float mnew = fmaxf(m, tmax);
        const float corr = __expf(m - mnew);
        l *= corr;
#pragma unroll
        for (int t = 0; t < 4; t++)
#pragma unroll
            for (int i = 0; i < 4; i++) o[t][i] *= corr;

#pragma unroll 8
        for (int kk = 0; kk < 32; kk++) {
            const float p = __expf(sc[kk] - mnew);
            l += p;
#pragma unroll
            for (int t = 0; t < 4; t++) {
                float4 vv = *(const float4*)&Vs[kk][t * 32 + sub * 4];
                o[t][0] = fmaf(p, vv.x, o[t][0]);
                o[t][1] = fmaf(p, vv.y, o[t][1]);
                o[t][2] = fmaf(p, vv.z, o[t][2]);
                o[t][3] = fmaf(p, vv.w, o[t][3]);
            }
        }
        m = mnew;
        __syncthreads();
    }

#pragma unroll
    for (int j = 0; j < LCK; j++) {
        const size_t off =
            (((size_t)(b * NKV + kvh) * LCK + j) * SS + q_global) * HD;
        const float* kp = ksuf + off;
        float p = 0.f;
#pragma unroll
        for (int t = 0; t < 4; t++) {
            float4 kv4 = *(const float4*)(kp + t * 32 + sub * 4);
            p = fmaf(qr[t][0], kv4.x, p);
            p = fmaf(qr[t][1], kv4.y, p);
            p = fmaf(qr[t][2], kv4.z, p);
            p = fmaf(qr[t][3], kv4.w, p);
        }
        p += __shfl_xor_sync(0xffffffffu, p, 1);
        p += __shfl_xor_sync(0xffffffffu, p, 2);
        p += __shfl_xor_sync(0xffffffffu, p, 4);

        const float mnew = fmaxf(m, p);
        const float corr = __expf(m - mnew);
        const float e = __expf(p - mnew);
        l = l * corr + e;
        const float* vp = vsuf + off;
#pragma unroll
        for (int t = 0; t < 4; t++) {
            float4 vv = *(const float4*)(vp + t * 32 + sub * 4);
            o[t][0] = o[t][0] * corr + e * vv.x;
            o[t][1] = o[t][1] * corr + e * vv.y;
            o[t][2] = o[t][2] * corr + e * vv.z;
            o[t][3] = o[t][3] * corr + e * vv.w;
        }
        m = mnew;
    }

    const float invl = qvalid ? (1.0f / l) : 0.0f;
    float* op = outbuf + (size_t)(b * SS + q_global) * QDIM + h * HD;
#pragma unroll
    for (int t = 0; t < 4; t++) {
        float4 w;
        w.x = o[t][0] * invl; w.y = o[t][1] * invl;
        w.z = o[t][2] * invl; w.w = o[t][3] * invl;
        *(float4*)(op + t * 32 + sub * 4) = w;
    }
}

// ---------------- launch ----------------------------------------------------
extern "C" void kernel_launch(void* const* d_in, const int* in_sizes, int n_in,
                              void* d_out, int out_size) {
    const float* x    = (const float*)d_in[0];
    const float* ksuf = (const float*)d_in[1];
    const float* vsuf = (const float*)d_in[2];
    const float* Wq   = (const float*)d_in[3];
    const float* Wk   = (const float*)d_in[4];
    const float* Wv   = (const float*)d_in[5];
    const float* Wo   = (const float*)d_in[6];
    const int* valid  = (const int*)d_in[7];
    float* out = (float*)d_out;

    float *gq, *gk, *gv, *ga;
    cudaGetSymbolAddress((void**)&gq, g_q);
    cudaGetSymbolAddress((void**)&gk, g_k);
    cudaGetSymbolAddress((void**)&gv, g_v);
    cudaGetSymbolAddress((void**)&ga, g_attn);

    cudaFuncSetAttribute(gemm_tf32,
                         cudaFuncAttributeMaxDynamicSharedMemorySize, GEMM_SMEM);

    dim3 blk(256);

    // projections (tensor cores, tf32)
    gemm_tf32<<<dim3(QDIM / BN, MROWS / BM), blk, GEMM_SMEM>>>(x, Wq, gq, MROWS, QDIM, HID);
    gemm_tf32<<<dim3(KVDIM / BN, MROWS / BM), blk, GEMM_SMEM>>>(x, Wk, gk, MROWS, KVDIM, HID);
    gemm_tf32<<<dim3(KVDIM / BN, MROWS / BM), blk, GEMM_SMEM>>>(x, Wv, gv, MROWS, KVDIM, HID);

    // RoPE on q and k
    rope_kernel<<<MROWS, 256>>>(gq, NH);
    rope_kernel<<<MROWS, 256>>>(gk, NKV);

    // attention
    attn_kernel<<<dim3(SS / 32, NH, BB), 256>>>(gq, gk, gv, ksuf, vsuf, valid, ga);

    // output projection (tensor cores, tf32)
    gemm_tf32<<<dim3(QDIM / BN, MROWS / BM), blk, GEMM_SMEM>>>(ga, Wo, out, MROWS, QDIM, HID);
}

// round 4
// speedup vs baseline: 2.5510x; 1.0519x over previous
#include <cuda_runtime.h>
#include <math.h>
#include <stdint.h>

#define BB 2
#define SS 1024
#define HID 4096
#define NH 32
#define NKV 8
#define HD 128
#define LCK 3
#define MROWS (BB*SS)   // 2048
#define QDIM (NH*HD)    // 4096
#define KVDIM (NKV*HD)  // 1024

// ---------------- scratch (static device globals; no allocations) ----------
__device__ float g_q[(size_t)MROWS * QDIM];     // 32 MB
__device__ float g_k[(size_t)MROWS * KVDIM];    // 8 MB
__device__ float g_v[(size_t)MROWS * KVDIM];    // 8 MB
__device__ float g_attn[(size_t)MROWS * QDIM];  // 32 MB
__device__ float g_xr[(size_t)MROWS * HID];     // 32 MB (tf32-rounded x)
__device__ float g_wq[(size_t)HID * QDIM];      // 64 MB rounded weights
__device__ float g_wk[(size_t)HID * KVDIM];     // 16 MB
__device__ float g_wv[(size_t)HID * KVDIM];     // 16 MB
__device__ float g_wo[(size_t)QDIM * HID];      // 64 MB

// ---------------- PTX helpers -----------------------------------------------
__device__ __forceinline__ void cp16(uint32_t dst, const void* src) {
    asm volatile("cp.async.cg.shared.global [%0], [%1], 16;" :: "r"(dst), "l"(src));
}
__device__ __forceinline__ float f2tf32(float x) {
    uint32_t u;
    asm("cvt.rna.tf32.f32 %0, %1;" : "=r"(u) : "f"(x));
    return __uint_as_float(u);
}
__device__ __forceinline__ void mma8(float* c, const uint32_t* a, const uint32_t* b) {
    asm volatile(
        "mma.sync.aligned.m16n8k8.row.col.f32.tf32.tf32.f32 "
        "{%0,%1,%2,%3},{%4,%5,%6,%7},{%8,%9},{%0,%1,%2,%3};"
        : "+f"(c[0]), "+f"(c[1]), "+f"(c[2]), "+f"(c[3])
        : "r"(a[0]), "r"(a[1]), "r"(a[2]), "r"(a[3]), "r"(b[0]), "r"(b[1]));
}
// packed f32x2
__device__ __forceinline__ unsigned long long fma2(unsigned long long a,
                                                   unsigned long long b,
                                                   unsigned long long c) {
    unsigned long long d;
    asm("fma.rn.f32x2 %0, %1, %2, %3;" : "=l"(d) : "l"(a), "l"(b), "l"(c));
    return d;
}
__device__ __forceinline__ unsigned long long mul2(unsigned long long a,
                                                   unsigned long long b) {
    unsigned long long d;
    asm("mul.rn.f32x2 %0, %1, %2;" : "=l"(d) : "l"(a), "l"(b));
    return d;
}
__device__ __forceinline__ unsigned long long pack2(float x) {
    unsigned long long d;
    asm("mov.b64 %0, {%1, %2};" : "=l"(d) : "f"(x), "f"(x));
    return d;
}
__device__ __forceinline__ void unpack2(unsigned long long v, float& lo, float& hi) {
    asm("mov.b64 {%0, %1}, %2;" : "=f"(lo), "=f"(hi) : "l"(v));
}

// ---------------- tf32 round pass --------------------------------------------
__global__ void round_tf32_kernel(const float4* __restrict__ in, float4* __restrict__ out) {
    const size_t i = (size_t)blockIdx.x * 256 + threadIdx.x;
    float4 v = in[i];
    v.x = f2tf32(v.x); v.y = f2tf32(v.y); v.z = f2tf32(v.z); v.w = f2tf32(v.w);
    out[i] = v;
}

// ---------------- legacy-mma TF32 GEMM ---------------------------------------
// C[M,N] = A[M,K] @ B[K,N].  A,B row-major, pre-rounded to tf32.
// Block tile BMt x 128, BK=32, 4 warps (2x2 warp grid), 3-stage cp.async.
template <int BMt>
__global__ __launch_bounds__(128) void gemm_lg(const float* __restrict__ A,
                                               const float* __restrict__ B,
                                               float* __restrict__ C,
                                               int M, int N, int K) {
    constexpr int BNt = 128;
    constexpr int WM = BMt / 2;         // 64 or 32
    constexpr int MT = WM / 16;         // 4 or 2
    constexpr int APITCH = 36;          // BK + 4
    constexpr int BPITCH = BNt + 4;     // 132
    constexpr int ASZ = BMt * APITCH;   // floats per A stage
    constexpr int BSZ = 32 * BPITCH;    // floats per B stage
    constexpr int STG = ASZ + BSZ;
    constexpr int ACH = BMt * 8;        // A float4 chunks per stage
    constexpr int BCH = 32 * (BNt / 4); // B float4 chunks per stage

    extern __shared__ float sm[];
    const uint32_t smb = (uint32_t)__cvta_generic_to_shared(sm);
    const uint32_t* s32 = (const uint32_t*)sm;

    const int tid  = threadIdx.x;
    const int lane = tid & 31;
    const int wid  = tid >> 5;
    const int gid  = lane >> 2;
    const int tig  = lane & 3;
    const int wm   = (wid & 1) * WM;
    const int wn   = (wid >> 1) * 64;

    const int bm0 = blockIdx.y * BMt;
    const int bn0 = blockIdx.x * BNt;

    float acc[MT][8][4];
#pragma unroll
    for (int mt = 0; mt < MT; mt++)
#pragma unroll
        for (int nt = 0; nt < 8; nt++)
#pragma unroll
            for (int i = 0; i < 4; i++) acc[mt][nt][i] = 0.f;

    const int T = K / 32;

    auto issue = [&](int t) {
        const int k0 = t * 32;
        const uint32_t sb = smb + (uint32_t)((t % 3) * STG * 4);
#pragma unroll
        for (int i = 0; i < ACH / 128; i++) {
            const int c = tid + i * 128;
            const int row = c >> 3;
            const int kq = (c & 7) * 4;
            cp16(sb + (uint32_t)((row * APITCH + kq) * 4),
                 A + (size_t)(bm0 + row) * K + k0 + kq);
        }
#pragma unroll
        for (int i = 0; i < BCH / 128; i++) {
            const int c = tid + i * 128;
            const int kk = c >> 5;
            const int n4 = (c & 31) * 4;
            cp16(sb + (uint32_t)((ASZ + kk * BPITCH + n4) * 4),
                 B + (size_t)(k0 + kk) * N + bn0 + n4);
        }
        asm volatile("cp.async.commit_group;");
    };

    issue(0);
    issue(1);

    for (int t = 0; t < T; t++) {
        if (t < T - 1) { asm volatile("cp.async.wait_group 1;"); }
        else           { asm volatile("cp.async.wait_group 0;"); }
        __syncthreads();
        if (t + 2 < T) issue(t + 2);

        const int so = (t % 3) * STG;
        const uint32_t* sa = s32 + so;
        const uint32_t* sb = s32 + so + ASZ;
#pragma unroll
        for (int ks = 0; ks < 32; ks += 8) {
            uint32_t af[MT][4];
#pragma unroll
            for (int mt = 0; mt < MT; mt++) {
                const int r = wm + mt * 16 + gid;
                af[mt][0] = sa[r * APITCH + ks + tig];
                af[mt][1] = sa[(r + 8) * APITCH + ks + tig];
                af[mt][2] = sa[r * APITCH + ks + tig + 4];
                af[mt][3] = sa[(r + 8) * APITCH + ks + tig + 4];
            }
            uint32_t bf[8][2];
#pragma unroll
            for (int nt = 0; nt < 8; nt++) {
                const int cc = wn + nt * 8 + gid;
                bf[nt][0] = sb[(ks + tig) * BPITCH + cc];
                bf[nt][1] = sb[(ks + tig + 4) * BPITCH + cc];
            }
#pragma unroll
            for (int mt = 0; mt < MT; mt++)
#pragma unroll
                for (int nt = 0; nt < 8; nt++)
                    mma8(acc[mt][nt], af[mt], bf[nt]);
        }
        __syncthreads();
    }

    // epilogue
#pragma unroll
    for (int mt = 0; mt < MT; mt++) {
#pragma unroll
        for (int nt = 0; nt < 8; nt++) {
            const int r = bm0 + wm + mt * 16 + gid;
            const int cc = bn0 + wn + nt * 8 + tig * 2;
            *(float2*)&C[(size_t)r * N + cc] =
                make_float2(acc[mt][nt][0], acc[mt][nt][1]);
            *(float2*)&C[(size_t)(r + 8) * N + cc] =
                make_float2(acc[mt][nt][2], acc[mt][nt][3]);
        }
    }
}

// ---------------- RoPE (fused q+k, in place) --------------------------------
__global__ void rope_fused(float* __restrict__ qb, float* __restrict__ kb) {
    const int row = blockIdx.x;
    const int which = blockIdx.y;
    float* buf = which ? kb : qb;
    const int heads = which ? NKV : NH;
    const int s = row & (SS - 1);
    const float log2theta = 13.287712379549449f;  // log2(10000)
    for (int idx = threadIdx.x; idx < heads * 64; idx += blockDim.x) {
        const int h = idx >> 6;
        const int i = idx & 63;
        const float inv = exp2f(-(float)(2 * i) * (1.0f / 128.0f) * log2theta);
        const float ang = (float)s * inv;
        const float c = cosf(ang);
        const float sn = sinf(ang);
        float* p = buf + (size_t)row * heads * HD + h * HD;
        const float x1 = p[i];
        const float x2 = p[i + 64];
        p[i]      = x1 * c - x2 * sn;
        p[i + 64] = x2 * c + x1 * sn;
    }
}

// ---------------- flash attention (fp32 via packed f32x2) --------------------
// grid (S/32, NH, B), block 256 = 32 q x 8 dim-lanes.
// Thread (ql,sub) owns dims d = t*32 + sub*4 + {0..3} (t=0..3) = 8 f32x2 pairs.
__global__ void attn_kernel(const float* __restrict__ q,
                            const float* __restrict__ k,
                            const float* __restrict__ v,
                            const float* __restrict__ ksuf,
                            const float* __restrict__ vsuf,
                            const int* __restrict__ validp,
                            float* __restrict__ outbuf) {
    __shared__ float Ks[32][128];
    __shared__ float Vs[32][128];

    const int valid = *validp;
    const int qt = blockIdx.x;
    const int h  = blockIdx.y;
    const int b  = blockIdx.z;
    const int kvh = h >> 2;

    const int tid = threadIdx.x;
    const int ql  = tid >> 3;
    const int sub = tid & 7;
    const int q_global = qt * 32 + ql;
    const bool qvalid = q_global < valid;

    const float scale = 0.08838834764831845f;
    const unsigned long long scale2 = pack2(scale);

    // q fragment: 8 packed pairs, pre-scaled
    unsigned long long q2[8];
    {
        const float* qp = q + (size_t)(b * SS + q_global) * QDIM + h * HD;
#pragma unroll
        for (int t = 0; t < 4; t++) {
            ulonglong2 u = *(const ulonglong2*)(qp + t * 32 + sub * 4);
            q2[2 * t]     = mul2(scale2, u.x);
            q2[2 * t + 1] = mul2(scale2, u.y);
        }
    }

    unsigned long long o2[8];
#pragma unroll
    for (int j = 0; j < 8; j++) o2[j] = 0ull;
    float m = -1e30f, l = 0.f;

    const int kend = qt * 32 + 32;
    const float* kb_base = k + (size_t)(b * SS) * KVDIM + kvh * HD;
    const float* vb_base = v + (size_t)(b * SS) * KVDIM + kvh * HD;

    for (int k0 = 0; k0 < kend; k0 += 32) {
#pragma unroll
        for (int t = 0; t < 4; t++) {
            const int f  = tid + t * 256;
            const int kk = f >> 5;
            const int d4 = (f & 31) * 4;
            *(float4*)&Ks[kk][d4] =
                *(const float4*)(kb_base + (size_t)(k0 + kk) * KVDIM + d4);
            *(float4*)&Vs[kk][d4] =
                *(const float4*)(vb_base + (size_t)(k0 + kk) * KVDIM + d4);
        }
        __syncthreads();

        float sc[32];
#pragma unroll 8
        for (int kk = 0; kk < 32; kk++) {
            unsigned long long p2 = 0ull;
#pragma unroll
            for (int t = 0; t < 4; t++) {
                ulonglong2 kv = *(const ulonglong2*)&Ks[kk][t * 32 + sub * 4];
                p2 = fma2(q2[2 * t], kv.x, p2);
                p2 = fma2(q2[2 * t + 1], kv.y, p2);
            }
            float plo, phi;
            unpack2(p2, plo, phi);
            float p = plo + phi;
            p += __shfl_xor_sync(0xffffffffu, p, 1);
            p += __shfl_xor_sync(0xffffffffu, p, 2);
            p += __shfl_xor_sync(0xffffffffu, p, 4);
            sc[kk] = (k0 + kk <= q_global) ? p : -1e30f;
        }

        float tmax = sc[0];
#pragma unroll
        for (int kk = 1; kk < 32; kk++) tmax = fmaxf(tmax, sc[kk]);
        const float mnew = fmaxf(m, tmax);
        const float corr = __expf(m - mnew);
        l *= corr;
        const unsigned long long corr2 = pack2(corr);
#pragma unroll
        for (int j = 0; j < 8; j++) o2[j] = mul2(corr2, o2[j]);

#pragma unroll 8
        for (int kk = 0; kk < 32; kk++) {
            const float p = __expf(sc[kk] - mnew);
            l += p;
            const unsigned long long p2 = pack2(p);
#pragma unroll
            for (int t = 0; t < 4; t++) {
                ulonglong2 vv = *(const ulonglong2*)&Vs[kk][t * 32 + sub * 4];
                o2[2 * t]     = fma2(p2, vv.x, o2[2 * t]);
                o2[2 * t + 1] = fma2(p2, vv.y, o2[2 * t + 1]);
            }
        }
        m = mnew;
        __syncthreads();
    }

    // ---- 3 suffix keys on the diagonal ----
#pragma unroll
    for (int j = 0; j < LCK; j++) {
        const size_t off =
            (((size_t)(b * NKV + kvh) * LCK + j) * SS + q_global) * HD;
        const float* kp = ksuf + off;
        unsigned long long p2 = 0ull;
#pragma unroll
        for (int t = 0; t < 4; t++) {
            ulonglong2 kv = *(const ulonglong2*)(kp + t * 32 + sub * 4);
            p2 = fma2(q2[2 * t], kv.x, p2);
            p2 = fma2(q2[2 * t + 1], kv.y, p2);
        }
        float plo, phi;
        unpack2(p2, plo, phi);
        float p = plo + phi;
        p += __shfl_xor_sync(0xffffffffu, p, 1);
        p += __shfl_xor_sync(0xffffffffu, p, 2);
        p += __shfl_xor_sync(0xffffffffu, p, 4);

        const float mnew = fmaxf(m, p);
        const float corr = __expf(m - mnew);
        const float e = __expf(p - mnew);
        l = l * corr + e;
        const unsigned long long corr2 = pack2(corr);
        const unsigned long long e2 = pack2(e);
        const float* vp = vsuf + off;
#pragma unroll
        for (int t = 0; t < 4; t++) {
            ulonglong2 vv = *(const ulonglong2*)(vp + t * 32 + sub * 4);
            o2[2 * t]     = fma2(e2, vv.x, mul2(corr2, o2[2 * t]));
            o2[2 * t + 1] = fma2(e2, vv.y, mul2(corr2, o2[2 * t + 1]));
        }
        m = mnew;
    }

    // epilogue: normalize, tf32-round (feeds the O projection), masked rows = 0
    const float invl = qvalid ? (1.0f / l) : 0.0f;
    float* op = outbuf + (size_t)(b * SS + q_global) * QDIM + h * HD;
#pragma unroll
    for (int t = 0; t < 4; t++) {
        float a0, a1, a2, a3;
        unpack2(o2[2 * t], a0, a1);
        unpack2(o2[2 * t + 1], a2, a3);
        float4 w;
        w.x = f2tf32(a0 * invl); w.y = f2tf32(a1 * invl);
        w.z = f2tf32(a2 * invl); w.w = f2tf32(a3 * invl);
        *(float4*)(op + t * 32 + sub * 4) = w;
    }
}

// ---------------- launch ----------------------------------------------------
extern "C" void kernel_launch(void* const* d_in, const int* in_sizes, int n_in,
                              void* d_out, int out_size) {
    const float* x    = (const float*)d_in[0];
    const float* ksuf = (const float*)d_in[1];
    const float* vsuf = (const float*)d_in[2];
    const float* Wq   = (const float*)d_in[3];
    const float* Wk   = (const float*)d_in[4];
    const float* Wv   = (const float*)d_in[5];
    const float* Wo   = (const float*)d_in[6];
    const int* valid  = (const int*)d_in[7];
    float* out = (float*)d_out;

    float *gq, *gk, *gv, *ga, *gxr, *wq, *wk, *wv, *wo;
    cudaGetSymbolAddress((void**)&gq, g_q);
    cudaGetSymbolAddress((void**)&gk, g_k);
    cudaGetSymbolAddress((void**)&gv, g_v);
    cudaGetSymbolAddress((void**)&ga, g_attn);
    cudaGetSymbolAddress((void**)&gxr, g_xr);
    cudaGetSymbolAddress((void**)&wq, g_wq);
    cudaGetSymbolAddress((void**)&wk, g_wk);
    cudaGetSymbolAddress((void**)&wv, g_wv);
    cudaGetSymbolAddress((void**)&wo, g_wo);

    // smem: 3 stages of (BMt*36 + 32*132) floats
    const int SMEM128 = 3 * (128 * 36 + 32 * 132) * 4;  // 105984
    const int SMEM64  = 3 * (64 * 36 + 32 * 132) * 4;   //  78336
    cudaFuncSetAttribute(gemm_lg<128>, cudaFuncAttributeMaxDynamicSharedMemorySize, SMEM128);
    cudaFuncSetAttribute(gemm_lg<64>,  cudaFuncAttributeMaxDynamicSharedMemorySize, SMEM64);

    // 0-4: tf32 rounding passes (rna; numerically identical to in-loop cvt)
    round_tf32_kernel<<<(MROWS * HID) / 1024, 256>>>((const float4*)x, (float4*)gxr);
    round_tf32_kernel<<<(HID * QDIM) / 1024, 256>>>((const float4*)Wq, (float4*)wq);
    round_tf32_kernel<<<(HID * KVDIM) / 1024, 256>>>((const float4*)Wk, (float4*)wk);
    round_tf32_kernel<<<(HID * KVDIM) / 1024, 256>>>((const float4*)Wv, (float4*)wv);
    round_tf32_kernel<<<(QDIM * HID) / 1024, 256>>>((const float4*)Wo, (float4*)wo);

    // 5: Q projection (ncu -s 5 captures this launch)
    gemm_lg<128><<<dim3(QDIM / 128, MROWS / 128), 128, SMEM128>>>(gxr, wq, gq, MROWS, QDIM, HID);
    // 6,7: K, V projections (smaller M-tile for better SM fill at N=1024)
    gemm_lg<64><<<dim3(KVDIM / 128, MROWS / 64), 128, SMEM64>>>(gxr, wk, gk, MROWS, KVDIM, HID);
    gemm_lg<64><<<dim3(KVDIM / 128, MROWS / 64), 128, SMEM64>>>(gxr, wv, gv, MROWS, KVDIM, HID);
    // 8: RoPE
    rope_fused<<<dim3(MROWS, 2), 256>>>(gq, gk);
    // 9: attention (writes tf32-rounded output)
    attn_kernel<<<dim3(SS / 32, NH, BB), 256>>>(gq, gk, gv, ksuf, vsuf, valid, ga);
    // 10: output projection
    gemm_lg<128><<<dim3(QDIM / 128, MROWS / 128), 128, SMEM128>>>(ga, wo, out, MROWS, QDIM, HID);
}